// round 1
// baseline (speedup 1.0000x reference)
#include <cuda_runtime.h>
#include <cuda_bf16.h>

// Problem constants
#define Bc 4
#define Sc 2048
#define Dc 1024
#define Hc 16
#define HDc 64
#define Mrows (Bc*Sc)   // 8192

// Device scratch (allowed: __device__ globals, no runtime allocation)
__device__ float g_Qh[(size_t)Bc*Hc*Sc*HDc];   // [B,H,S,64]
__device__ float g_Kh[(size_t)Bc*Hc*Sc*HDc];
__device__ float g_Vh[(size_t)Bc*Hc*Sc*HDc];
__device__ float g_ctx[(size_t)Bc*Sc*Dc];      // [B,S,D]

// ---------------------------------------------------------------------------
// Tiled SGEMM: out[m,n] = sum_k X[m,k] * W[n,k] + bias[n]
// X: [8192,1024] row-major, W: [1024,1024] row-major (torch Linear weight)
// OUT_MODE 0: scatter to head layout [B,H,S,64]; OUT_MODE 1: plain [m,n]
// ---------------------------------------------------------------------------
template <int OUT_MODE>
__global__ __launch_bounds__(256)
void gemm_bias_kernel(const float* __restrict__ X,
                      const float* __restrict__ W,
                      const float* __restrict__ bias,
                      float* __restrict__ out)
{
    constexpr int BM = 128, BN = 128, BK = 16;
    __shared__ float As[BK][BM];
    __shared__ float Bs[BK][BN];

    const int t  = threadIdx.x;
    const int tx = t & 15;        // 0..15  (n direction)
    const int ty = t >> 4;        // 0..15  (m direction)
    const int m0 = blockIdx.y * BM;
    const int n0 = blockIdx.x * BN;

    const float* Aptr = X + (size_t)m0 * 1024;
    const float* Bptr = W + (size_t)n0 * 1024;

    float c[8][8];
#pragma unroll
    for (int i = 0; i < 8; ++i)
#pragma unroll
        for (int j = 0; j < 8; ++j) c[i][j] = 0.0f;

    for (int k0 = 0; k0 < 1024; k0 += BK) {
        // Stage A and B tiles (each 128x16 floats = 512 float4; 2 per thread)
#pragma unroll
        for (int p = 0; p < 2; ++p) {
            int f   = t + p * 256;
            int row = f >> 2;            // 0..127
            int c4  = (f & 3) << 2;      // 0,4,8,12
            float4 va = *reinterpret_cast<const float4*>(Aptr + (size_t)row * 1024 + k0 + c4);
            As[c4 + 0][row] = va.x; As[c4 + 1][row] = va.y;
            As[c4 + 2][row] = va.z; As[c4 + 3][row] = va.w;
            float4 vb = *reinterpret_cast<const float4*>(Bptr + (size_t)row * 1024 + k0 + c4);
            Bs[c4 + 0][row] = vb.x; Bs[c4 + 1][row] = vb.y;
            Bs[c4 + 2][row] = vb.z; Bs[c4 + 3][row] = vb.w;
        }
        __syncthreads();

#pragma unroll
        for (int kk = 0; kk < BK; ++kk) {
            float4 a0 = *reinterpret_cast<const float4*>(&As[kk][ty * 8]);
            float4 a1 = *reinterpret_cast<const float4*>(&As[kk][ty * 8 + 4]);
            float4 b0 = *reinterpret_cast<const float4*>(&Bs[kk][tx * 8]);
            float4 b1 = *reinterpret_cast<const float4*>(&Bs[kk][tx * 8 + 4]);
            float a[8] = {a0.x, a0.y, a0.z, a0.w, a1.x, a1.y, a1.z, a1.w};
            float b[8] = {b0.x, b0.y, b0.z, b0.w, b1.x, b1.y, b1.z, b1.w};
#pragma unroll
            for (int i = 0; i < 8; ++i)
#pragma unroll
                for (int j = 0; j < 8; ++j)
                    c[i][j] = fmaf(a[i], b[j], c[i][j]);
        }
        __syncthreads();
    }

    // Epilogue
#pragma unroll
    for (int i = 0; i < 8; ++i) {
        int m = m0 + ty * 8 + i;
#pragma unroll
        for (int j = 0; j < 8; ++j) {
            int n = n0 + tx * 8 + j;
            float val = c[i][j] + bias[n];
            if (OUT_MODE == 0) {
                int b  = m >> 11;        // /2048
                int s  = m & 2047;
                int h  = n >> 6;
                int hd = n & 63;
                out[(((size_t)(b * Hc + h)) * Sc + s) * HDc + hd] = val;
            } else {
                out[(size_t)m * Dc + n] = val;
            }
        }
    }
}

// ---------------------------------------------------------------------------
// Flash attention (causal), fp32. Grid: (S/64, B*H). 256 threads.
// Each thread owns a 4x4 tile of the 64x64 (q-rows x hd-cols) output.
// ---------------------------------------------------------------------------
#define ATTN_PAD 65
#define ATTN_SMEM (4 * 64 * ATTN_PAD * (int)sizeof(float))  // 66560 bytes

__global__ __launch_bounds__(256)
void attn_kernel(const float* __restrict__ Qh,
                 const float* __restrict__ Kh,
                 const float* __restrict__ Vh,
                 float* __restrict__ ctx)
{
    extern __shared__ float sm[];
    float (*Qs)[ATTN_PAD] = reinterpret_cast<float(*)[ATTN_PAD]>(sm);
    float (*Ks)[ATTN_PAD] = reinterpret_cast<float(*)[ATTN_PAD]>(sm + 64 * ATTN_PAD);
    float (*Vs)[ATTN_PAD] = reinterpret_cast<float(*)[ATTN_PAD]>(sm + 2 * 64 * ATTN_PAD);
    float (*Ps)[ATTN_PAD] = reinterpret_cast<float(*)[ATTN_PAD]>(sm + 3 * 64 * ATTN_PAD);

    const int bh = blockIdx.y;            // 0..63
    const int qt = blockIdx.x;            // 0..31
    const int q0 = qt * 64;
    const int t  = threadIdx.x;
    const int tx = t & 15;                // col group (hd / k-col)
    const int ty = t >> 4;                // row group (q rows)

    const float* Qb = Qh + (size_t)bh * Sc * HDc;
    const float* Kb = Kh + (size_t)bh * Sc * HDc;
    const float* Vb = Vh + (size_t)bh * Sc * HDc;

    // Load Q tile (64x64), pre-scaled by 1/sqrt(64) = 0.125
    for (int i = t; i < 64 * 64; i += 256) {
        int r = i >> 6, d = i & 63;
        Qs[r][d] = Qb[(size_t)(q0 + r) * HDc + d] * 0.125f;
    }

    float m_i[4], l_i[4], acc[4][4];
#pragma unroll
    for (int i = 0; i < 4; ++i) {
        m_i[i] = -1e30f; l_i[i] = 0.0f;
#pragma unroll
        for (int j = 0; j < 4; ++j) acc[i][j] = 0.0f;
    }

    for (int kt = 0; kt <= qt; ++kt) {
        const int k0 = kt * 64;
        __syncthreads();  // previous tile's Vs/Ps consumers done (also covers Qs load)

        // Load K,V tiles (coalesced: 64 contiguous floats per row)
        for (int i = t; i < 64 * 64; i += 256) {
            int r = i >> 6, d = i & 63;
            Ks[r][d] = Kb[(size_t)(k0 + r) * HDc + d];
            Vs[r][d] = Vb[(size_t)(k0 + r) * HDc + d];
        }
        __syncthreads();

        // s[i][j] = q_row(ty*4+i) . k_row(tx*4+j)
        float s[4][4];
#pragma unroll
        for (int i = 0; i < 4; ++i)
#pragma unroll
            for (int j = 0; j < 4; ++j) s[i][j] = 0.0f;

#pragma unroll 8
        for (int d = 0; d < 64; ++d) {
            float a0 = Qs[ty * 4 + 0][d], a1 = Qs[ty * 4 + 1][d];
            float a2 = Qs[ty * 4 + 2][d], a3 = Qs[ty * 4 + 3][d];
            float b0 = Ks[tx * 4 + 0][d], b1 = Ks[tx * 4 + 1][d];
            float b2 = Ks[tx * 4 + 2][d], b3 = Ks[tx * 4 + 3][d];
            s[0][0] = fmaf(a0, b0, s[0][0]); s[0][1] = fmaf(a0, b1, s[0][1]);
            s[0][2] = fmaf(a0, b2, s[0][2]); s[0][3] = fmaf(a0, b3, s[0][3]);
            s[1][0] = fmaf(a1, b0, s[1][0]); s[1][1] = fmaf(a1, b1, s[1][1]);
            s[1][2] = fmaf(a1, b2, s[1][2]); s[1][3] = fmaf(a1, b3, s[1][3]);
            s[2][0] = fmaf(a2, b0, s[2][0]); s[2][1] = fmaf(a2, b1, s[2][1]);
            s[2][2] = fmaf(a2, b2, s[2][2]); s[2][3] = fmaf(a2, b3, s[2][3]);
            s[3][0] = fmaf(a3, b0, s[3][0]); s[3][1] = fmaf(a3, b1, s[3][1]);
            s[3][2] = fmaf(a3, b2, s[3][2]); s[3][3] = fmaf(a3, b3, s[3][3]);
        }

        // Causal mask only needed on the diagonal tile
        if (kt == qt) {
#pragma unroll
            for (int i = 0; i < 4; ++i)
#pragma unroll
                for (int j = 0; j < 4; ++j)
                    if (tx * 4 + j > ty * 4 + i) s[i][j] = -1e30f;
        }

        // Online softmax (row stats reduced across the 16 tx threads of each ty)
#pragma unroll
        for (int i = 0; i < 4; ++i) {
            float mm = fmaxf(fmaxf(s[i][0], s[i][1]), fmaxf(s[i][2], s[i][3]));
#pragma unroll
            for (int o = 1; o < 16; o <<= 1)
                mm = fmaxf(mm, __shfl_xor_sync(0xffffffffu, mm, o));
            float mnew = fmaxf(m_i[i], mm);
            float csc  = __expf(m_i[i] - mnew);
            float lad  = 0.0f;
            float p0 = __expf(s[i][0] - mnew);
            float p1 = __expf(s[i][1] - mnew);
            float p2 = __expf(s[i][2] - mnew);
            float p3 = __expf(s[i][3] - mnew);
            lad = p0 + p1 + p2 + p3;
#pragma unroll
            for (int o = 1; o < 16; o <<= 1)
                lad += __shfl_xor_sync(0xffffffffu, lad, o);
            l_i[i] = l_i[i] * csc + lad;
            m_i[i] = mnew;
#pragma unroll
            for (int j = 0; j < 4; ++j) acc[i][j] *= csc;
            Ps[ty * 4 + i][tx * 4 + 0] = p0;
            Ps[ty * 4 + i][tx * 4 + 1] = p1;
            Ps[ty * 4 + i][tx * 4 + 2] = p2;
            Ps[ty * 4 + i][tx * 4 + 3] = p3;
        }
        __syncthreads();

        // acc += P @ V
#pragma unroll 8
        for (int kk = 0; kk < 64; ++kk) {
            float a0 = Ps[ty * 4 + 0][kk], a1 = Ps[ty * 4 + 1][kk];
            float a2 = Ps[ty * 4 + 2][kk], a3 = Ps[ty * 4 + 3][kk];
            float b0 = Vs[kk][tx * 4 + 0], b1 = Vs[kk][tx * 4 + 1];
            float b2 = Vs[kk][tx * 4 + 2], b3 = Vs[kk][tx * 4 + 3];
            acc[0][0] = fmaf(a0, b0, acc[0][0]); acc[0][1] = fmaf(a0, b1, acc[0][1]);
            acc[0][2] = fmaf(a0, b2, acc[0][2]); acc[0][3] = fmaf(a0, b3, acc[0][3]);
            acc[1][0] = fmaf(a1, b0, acc[1][0]); acc[1][1] = fmaf(a1, b1, acc[1][1]);
            acc[1][2] = fmaf(a1, b2, acc[1][2]); acc[1][3] = fmaf(a1, b3, acc[1][3]);
            acc[2][0] = fmaf(a2, b0, acc[2][0]); acc[2][1] = fmaf(a2, b1, acc[2][1]);
            acc[2][2] = fmaf(a2, b2, acc[2][2]); acc[2][3] = fmaf(a2, b3, acc[2][3]);
            acc[3][0] = fmaf(a3, b0, acc[3][0]); acc[3][1] = fmaf(a3, b1, acc[3][1]);
            acc[3][2] = fmaf(a3, b2, acc[3][2]); acc[3][3] = fmaf(a3, b3, acc[3][3]);
        }
    }

    // Write context in [B,S,D] layout (D = h*64 + hd)
    const int b = bh >> 4;
    const int h = bh & 15;
#pragma unroll
    for (int i = 0; i < 4; ++i) {
        float inv = 1.0f / l_i[i];
        int srow = q0 + ty * 4 + i;
#pragma unroll
        for (int j = 0; j < 4; ++j) {
            ctx[((size_t)(b * Sc + srow)) * Dc + h * 64 + tx * 4 + j] = acc[i][j] * inv;
        }
    }
}

// ---------------------------------------------------------------------------
// Launch
// ---------------------------------------------------------------------------
extern "C" void kernel_launch(void* const* d_in, const int* in_sizes, int n_in,
                              void* d_out, int out_size)
{
    const float* q  = (const float*)d_in[0];
    const float* k  = (const float*)d_in[1];
    const float* v  = (const float*)d_in[2];
    // d_in[3] = mask (causal, hardcoded in attention kernel)
    const float* Wq = (const float*)d_in[4];
    const float* bq = (const float*)d_in[5];
    const float* Wk = (const float*)d_in[6];
    const float* bk = (const float*)d_in[7];
    const float* Wv = (const float*)d_in[8];
    const float* bv = (const float*)d_in[9];
    const float* Wo = (const float*)d_in[10];
    const float* bo = (const float*)d_in[11];
    float* out = (float*)d_out;

    void *pQ, *pK, *pV, *pC;
    cudaGetSymbolAddress(&pQ, g_Qh);
    cudaGetSymbolAddress(&pK, g_Kh);
    cudaGetSymbolAddress(&pV, g_Vh);
    cudaGetSymbolAddress(&pC, g_ctx);

    cudaFuncSetAttribute(attn_kernel, cudaFuncAttributeMaxDynamicSharedMemorySize, ATTN_SMEM);

    dim3 gg(Dc / 128, Mrows / 128);   // (8, 64)
    gemm_bias_kernel<0><<<gg, 256>>>(q, Wq, bq, (float*)pQ);
    gemm_bias_kernel<0><<<gg, 256>>>(k, Wk, bk, (float*)pK);
    gemm_bias_kernel<0><<<gg, 256>>>(v, Wv, bv, (float*)pV);

    dim3 ga(Sc / 64, Bc * Hc);        // (32, 64)
    attn_kernel<<<ga, 256, ATTN_SMEM>>>((const float*)pQ, (const float*)pK,
                                        (const float*)pV, (float*)pC);

    gemm_bias_kernel<1><<<gg, 256>>>((const float*)pC, Wo, bo, out);
}

// round 2
// speedup vs baseline: 1.6192x; 1.6192x over previous
#include <cuda_runtime.h>
#include <cuda_bf16.h>

// Problem constants
#define Bc 4
#define Sc 2048
#define Dc 1024
#define Hc 16
#define HDc 64
#define Mrows (Bc*Sc)   // 8192

// Device scratch
__device__ float g_Qh[(size_t)Bc*Hc*Sc*HDc];   // [B,H,S,64]
__device__ float g_Kh[(size_t)Bc*Hc*Sc*HDc];
__device__ float g_Vh[(size_t)Bc*Hc*Sc*HDc];
__device__ float g_ctx[(size_t)Bc*Sc*Dc];      // [B,S,D]

// ---------------------------------------------------------------------------
// bf16 split helpers: x ~= hi + lo, both bf16. Pack k-adjacent pairs into u32.
// ---------------------------------------------------------------------------
__device__ __forceinline__ void split_pair(float x0, float x1,
                                           unsigned& hi, unsigned& lo)
{
    __nv_bfloat16 h0 = __float2bfloat16_rn(x0);
    __nv_bfloat16 h1 = __float2bfloat16_rn(x1);
    float r0 = x0 - __bfloat162float(h0);
    float r1 = x1 - __bfloat162float(h1);
    __nv_bfloat16 l0 = __float2bfloat16_rn(r0);
    __nv_bfloat16 l1 = __float2bfloat16_rn(r1);
    unsigned uh0 = __bfloat16_as_ushort(h0), uh1 = __bfloat16_as_ushort(h1);
    unsigned ul0 = __bfloat16_as_ushort(l0), ul1 = __bfloat16_as_ushort(l1);
    hi = (uh1 << 16) | uh0;
    lo = (ul1 << 16) | ul0;
}

__device__ __forceinline__ void mma16816(float c[4], const unsigned a[4],
                                         const unsigned b[2])
{
    asm volatile(
        "mma.sync.aligned.m16n8k16.row.col.f32.bf16.bf16.f32 "
        "{%0,%1,%2,%3}, {%4,%5,%6,%7}, {%8,%9}, {%0,%1,%2,%3};\n"
        : "+f"(c[0]), "+f"(c[1]), "+f"(c[2]), "+f"(c[3])
        : "r"(a[0]), "r"(a[1]), "r"(a[2]), "r"(a[3]),
          "r"(b[0]), "r"(b[1]));
}

// ---------------------------------------------------------------------------
// Tensor-core SGEMM via bf16x3: out[m,n] = sum_k X[m,k]*W[n,k] + bias[n]
// X: [8192,1024] rm, W: [1024,1024] rm. Block 128x128, BK=32, 8 warps (2x4).
// OUT_MODE 0: scatter to [B,H,S,64]; OUT_MODE 1: plain [m,n].
// ---------------------------------------------------------------------------
#define KP 20   // u32 stride per row: 16 data pairs + 4 pad (conflict-free)

template <int OUT_MODE>
__global__ __launch_bounds__(256, 1)
void gemm_mma_kernel(const float* __restrict__ X,
                     const float* __restrict__ W,
                     const float* __restrict__ bias,
                     float* __restrict__ out)
{
    __shared__ unsigned As_hi[128][KP];
    __shared__ unsigned As_lo[128][KP];
    __shared__ unsigned Bs_hi[128][KP];
    __shared__ unsigned Bs_lo[128][KP];

    const int t    = threadIdx.x;
    const int lane = t & 31;
    const int wid  = t >> 5;            // 0..7
    const int wm   = wid >> 2;          // 0..1  -> m offset 64*wm
    const int wn   = wid & 3;           // 0..3  -> n offset 32*wn
    const int g    = lane >> 2;         // group 0..7
    const int tig  = lane & 3;          // 0..3

    const int m0 = blockIdx.y * 128;
    const int n0 = blockIdx.x * 128;

    const float* Aptr = X + (size_t)m0 * 1024;
    const float* Bptr = W + (size_t)n0 * 1024;

    // staging slot geometry: 1024 float4 slots per matrix per tile, 4/thread
    int srow[4], scol[4];
#pragma unroll
    for (int p = 0; p < 4; ++p) {
        int slot = t + p * 256;
        srow[p] = slot >> 3;            // 0..127
        scol[p] = (slot & 7) << 2;      // 0,4,..,28
    }

    float c[4][4][4];
#pragma unroll
    for (int i = 0; i < 4; ++i)
#pragma unroll
        for (int j = 0; j < 4; ++j)
#pragma unroll
            for (int e = 0; e < 4; ++e) c[i][j][e] = 0.0f;

    // prefetch tile 0 into registers
    float4 ar[4], br[4];
#pragma unroll
    for (int p = 0; p < 4; ++p) {
        ar[p] = *reinterpret_cast<const float4*>(Aptr + (size_t)srow[p] * 1024 + scol[p]);
        br[p] = *reinterpret_cast<const float4*>(Bptr + (size_t)srow[p] * 1024 + scol[p]);
    }

    const int NT = 1024 / 32;           // 32 k-tiles
    for (int kt = 0; kt < NT; ++kt) {
        // store staged regs -> smem (split bf16 hi/lo)
#pragma unroll
        for (int p = 0; p < 4; ++p) {
            int r = srow[p], cp = scol[p] >> 1;   // pair index base
            unsigned h0, l0, h1, l1;
            split_pair(ar[p].x, ar[p].y, h0, l0);
            split_pair(ar[p].z, ar[p].w, h1, l1);
            As_hi[r][cp] = h0; As_hi[r][cp + 1] = h1;
            As_lo[r][cp] = l0; As_lo[r][cp + 1] = l1;
            split_pair(br[p].x, br[p].y, h0, l0);
            split_pair(br[p].z, br[p].w, h1, l1);
            Bs_hi[r][cp] = h0; Bs_hi[r][cp + 1] = h1;
            Bs_lo[r][cp] = l0; Bs_lo[r][cp + 1] = l1;
        }
        __syncthreads();

        // prefetch next tile while computing this one
        if (kt + 1 < NT) {
            int k0 = (kt + 1) * 32;
#pragma unroll
            for (int p = 0; p < 4; ++p) {
                ar[p] = *reinterpret_cast<const float4*>(Aptr + (size_t)srow[p] * 1024 + k0 + scol[p]);
                br[p] = *reinterpret_cast<const float4*>(Bptr + (size_t)srow[p] * 1024 + k0 + scol[p]);
            }
        }

        // two k16 steps
#pragma unroll
        for (int ks = 0; ks < 2; ++ks) {
            const int pb = ks * 8;
            unsigned ahi[4][4], alo[4][4];
#pragma unroll
            for (int mf = 0; mf < 4; ++mf) {
                int r = wm * 64 + mf * 16 + g;
                ahi[mf][0] = As_hi[r][pb + tig];
                ahi[mf][1] = As_hi[r + 8][pb + tig];
                ahi[mf][2] = As_hi[r][pb + tig + 4];
                ahi[mf][3] = As_hi[r + 8][pb + tig + 4];
                alo[mf][0] = As_lo[r][pb + tig];
                alo[mf][1] = As_lo[r + 8][pb + tig];
                alo[mf][2] = As_lo[r][pb + tig + 4];
                alo[mf][3] = As_lo[r + 8][pb + tig + 4];
            }
            unsigned bhi[4][2], blo[4][2];
#pragma unroll
            for (int nf = 0; nf < 4; ++nf) {
                int cn = wn * 32 + nf * 8 + g;
                bhi[nf][0] = Bs_hi[cn][pb + tig];
                bhi[nf][1] = Bs_hi[cn][pb + tig + 4];
                blo[nf][0] = Bs_lo[cn][pb + tig];
                blo[nf][1] = Bs_lo[cn][pb + tig + 4];
            }
#pragma unroll
            for (int mf = 0; mf < 4; ++mf)
#pragma unroll
                for (int nf = 0; nf < 4; ++nf) {
                    mma16816(c[mf][nf], ahi[mf], bhi[nf]);
                    mma16816(c[mf][nf], ahi[mf], blo[nf]);
                    mma16816(c[mf][nf], alo[mf], bhi[nf]);
                }
        }
        __syncthreads();
    }

    // Epilogue
#pragma unroll
    for (int mf = 0; mf < 4; ++mf) {
#pragma unroll
        for (int nf = 0; nf < 4; ++nf) {
            int m  = m0 + wm * 64 + mf * 16 + g;
            int n  = n0 + wn * 32 + nf * 8 + tig * 2;
            float v0 = c[mf][nf][0] + bias[n];
            float v1 = c[mf][nf][1] + bias[n + 1];
            float v2 = c[mf][nf][2] + bias[n];
            float v3 = c[mf][nf][3] + bias[n + 1];
            if (OUT_MODE == 0) {
                int b = m >> 11, s = m & 2047;
                int h = n >> 6, hd = n & 63;
                size_t base = (((size_t)(b * Hc + h)) * Sc + s) * HDc + hd;
                out[base]     = v0;
                out[base + 1] = v1;
                int m2 = m + 8;
                size_t base2 = (((size_t)(b * Hc + h)) * Sc + (m2 & 2047)) * HDc + hd;
                out[base2]     = v2;
                out[base2 + 1] = v3;
            } else {
                out[(size_t)m * Dc + n]       = v0;
                out[(size_t)m * Dc + n + 1]   = v1;
                out[(size_t)(m + 8) * Dc + n]     = v2;
                out[(size_t)(m + 8) * Dc + n + 1] = v3;
            }
        }
    }
}

// ---------------------------------------------------------------------------
// Flash attention (causal), fp32 SIMT (unchanged from R1).
// ---------------------------------------------------------------------------
#define ATTN_PAD 65
#define ATTN_SMEM (4 * 64 * ATTN_PAD * (int)sizeof(float))

__global__ __launch_bounds__(256)
void attn_kernel(const float* __restrict__ Qh,
                 const float* __restrict__ Kh,
                 const float* __restrict__ Vh,
                 float* __restrict__ ctx)
{
    extern __shared__ float sm[];
    float (*Qs)[ATTN_PAD] = reinterpret_cast<float(*)[ATTN_PAD]>(sm);
    float (*Ks)[ATTN_PAD] = reinterpret_cast<float(*)[ATTN_PAD]>(sm + 64 * ATTN_PAD);
    float (*Vs)[ATTN_PAD] = reinterpret_cast<float(*)[ATTN_PAD]>(sm + 2 * 64 * ATTN_PAD);
    float (*Ps)[ATTN_PAD] = reinterpret_cast<float(*)[ATTN_PAD]>(sm + 3 * 64 * ATTN_PAD);

    const int bh = blockIdx.y;
    const int qt = blockIdx.x;
    const int q0 = qt * 64;
    const int t  = threadIdx.x;
    const int tx = t & 15;
    const int ty = t >> 4;

    const float* Qb = Qh + (size_t)bh * Sc * HDc;
    const float* Kb = Kh + (size_t)bh * Sc * HDc;
    const float* Vb = Vh + (size_t)bh * Sc * HDc;

    for (int i = t; i < 64 * 64; i += 256) {
        int r = i >> 6, d = i & 63;
        Qs[r][d] = Qb[(size_t)(q0 + r) * HDc + d] * 0.125f;
    }

    float m_i[4], l_i[4], acc[4][4];
#pragma unroll
    for (int i = 0; i < 4; ++i) {
        m_i[i] = -1e30f; l_i[i] = 0.0f;
#pragma unroll
        for (int j = 0; j < 4; ++j) acc[i][j] = 0.0f;
    }

    for (int kt = 0; kt <= qt; ++kt) {
        const int k0 = kt * 64;
        __syncthreads();

        for (int i = t; i < 64 * 64; i += 256) {
            int r = i >> 6, d = i & 63;
            Ks[r][d] = Kb[(size_t)(k0 + r) * HDc + d];
            Vs[r][d] = Vb[(size_t)(k0 + r) * HDc + d];
        }
        __syncthreads();

        float s[4][4];
#pragma unroll
        for (int i = 0; i < 4; ++i)
#pragma unroll
            for (int j = 0; j < 4; ++j) s[i][j] = 0.0f;

#pragma unroll 8
        for (int d = 0; d < 64; ++d) {
            float a0 = Qs[ty * 4 + 0][d], a1 = Qs[ty * 4 + 1][d];
            float a2 = Qs[ty * 4 + 2][d], a3 = Qs[ty * 4 + 3][d];
            float b0 = Ks[tx * 4 + 0][d], b1 = Ks[tx * 4 + 1][d];
            float b2 = Ks[tx * 4 + 2][d], b3 = Ks[tx * 4 + 3][d];
            s[0][0] = fmaf(a0, b0, s[0][0]); s[0][1] = fmaf(a0, b1, s[0][1]);
            s[0][2] = fmaf(a0, b2, s[0][2]); s[0][3] = fmaf(a0, b3, s[0][3]);
            s[1][0] = fmaf(a1, b0, s[1][0]); s[1][1] = fmaf(a1, b1, s[1][1]);
            s[1][2] = fmaf(a1, b2, s[1][2]); s[1][3] = fmaf(a1, b3, s[1][3]);
            s[2][0] = fmaf(a2, b0, s[2][0]); s[2][1] = fmaf(a2, b1, s[2][1]);
            s[2][2] = fmaf(a2, b2, s[2][2]); s[2][3] = fmaf(a2, b3, s[2][3]);
            s[3][0] = fmaf(a3, b0, s[3][0]); s[3][1] = fmaf(a3, b1, s[3][1]);
            s[3][2] = fmaf(a3, b2, s[3][2]); s[3][3] = fmaf(a3, b3, s[3][3]);
        }

        if (kt == qt) {
#pragma unroll
            for (int i = 0; i < 4; ++i)
#pragma unroll
                for (int j = 0; j < 4; ++j)
                    if (tx * 4 + j > ty * 4 + i) s[i][j] = -1e30f;
        }

#pragma unroll
        for (int i = 0; i < 4; ++i) {
            float mm = fmaxf(fmaxf(s[i][0], s[i][1]), fmaxf(s[i][2], s[i][3]));
#pragma unroll
            for (int o = 1; o < 16; o <<= 1)
                mm = fmaxf(mm, __shfl_xor_sync(0xffffffffu, mm, o));
            float mnew = fmaxf(m_i[i], mm);
            float csc  = __expf(m_i[i] - mnew);
            float p0 = __expf(s[i][0] - mnew);
            float p1 = __expf(s[i][1] - mnew);
            float p2 = __expf(s[i][2] - mnew);
            float p3 = __expf(s[i][3] - mnew);
            float lad = p0 + p1 + p2 + p3;
#pragma unroll
            for (int o = 1; o < 16; o <<= 1)
                lad += __shfl_xor_sync(0xffffffffu, lad, o);
            l_i[i] = l_i[i] * csc + lad;
            m_i[i] = mnew;
#pragma unroll
            for (int j = 0; j < 4; ++j) acc[i][j] *= csc;
            Ps[ty * 4 + i][tx * 4 + 0] = p0;
            Ps[ty * 4 + i][tx * 4 + 1] = p1;
            Ps[ty * 4 + i][tx * 4 + 2] = p2;
            Ps[ty * 4 + i][tx * 4 + 3] = p3;
        }
        __syncthreads();

#pragma unroll 8
        for (int kk = 0; kk < 64; ++kk) {
            float a0 = Ps[ty * 4 + 0][kk], a1 = Ps[ty * 4 + 1][kk];
            float a2 = Ps[ty * 4 + 2][kk], a3 = Ps[ty * 4 + 3][kk];
            float b0 = Vs[kk][tx * 4 + 0], b1 = Vs[kk][tx * 4 + 1];
            float b2 = Vs[kk][tx * 4 + 2], b3 = Vs[kk][tx * 4 + 3];
            acc[0][0] = fmaf(a0, b0, acc[0][0]); acc[0][1] = fmaf(a0, b1, acc[0][1]);
            acc[0][2] = fmaf(a0, b2, acc[0][2]); acc[0][3] = fmaf(a0, b3, acc[0][3]);
            acc[1][0] = fmaf(a1, b0, acc[1][0]); acc[1][1] = fmaf(a1, b1, acc[1][1]);
            acc[1][2] = fmaf(a1, b2, acc[1][2]); acc[1][3] = fmaf(a1, b3, acc[1][3]);
            acc[2][0] = fmaf(a2, b0, acc[2][0]); acc[2][1] = fmaf(a2, b1, acc[2][1]);
            acc[2][2] = fmaf(a2, b2, acc[2][2]); acc[2][3] = fmaf(a2, b3, acc[2][3]);
            acc[3][0] = fmaf(a3, b0, acc[3][0]); acc[3][1] = fmaf(a3, b1, acc[3][1]);
            acc[3][2] = fmaf(a3, b2, acc[3][2]); acc[3][3] = fmaf(a3, b3, acc[3][3]);
        }
    }

    const int b = bh >> 4;
    const int h = bh & 15;
#pragma unroll
    for (int i = 0; i < 4; ++i) {
        float inv = 1.0f / l_i[i];
        int srw = q0 + ty * 4 + i;
#pragma unroll
        for (int j = 0; j < 4; ++j) {
            ctx[((size_t)(b * Sc + srw)) * Dc + h * 64 + tx * 4 + j] = acc[i][j] * inv;
        }
    }
}

// ---------------------------------------------------------------------------
// Launch
// ---------------------------------------------------------------------------
extern "C" void kernel_launch(void* const* d_in, const int* in_sizes, int n_in,
                              void* d_out, int out_size)
{
    const float* q  = (const float*)d_in[0];
    const float* k  = (const float*)d_in[1];
    const float* v  = (const float*)d_in[2];
    const float* Wq = (const float*)d_in[4];
    const float* bq = (const float*)d_in[5];
    const float* Wk = (const float*)d_in[6];
    const float* bk = (const float*)d_in[7];
    const float* Wv = (const float*)d_in[8];
    const float* bv = (const float*)d_in[9];
    const float* Wo = (const float*)d_in[10];
    const float* bo = (const float*)d_in[11];
    float* out = (float*)d_out;

    void *pQ, *pK, *pV, *pC;
    cudaGetSymbolAddress(&pQ, g_Qh);
    cudaGetSymbolAddress(&pK, g_Kh);
    cudaGetSymbolAddress(&pV, g_Vh);
    cudaGetSymbolAddress(&pC, g_ctx);

    cudaFuncSetAttribute(attn_kernel, cudaFuncAttributeMaxDynamicSharedMemorySize, ATTN_SMEM);

    dim3 gg(Dc / 128, Mrows / 128);   // (8, 64)
    gemm_mma_kernel<0><<<gg, 256>>>(q, Wq, bq, (float*)pQ);
    gemm_mma_kernel<0><<<gg, 256>>>(k, Wk, bk, (float*)pK);
    gemm_mma_kernel<0><<<gg, 256>>>(v, Wv, bv, (float*)pV);

    dim3 ga(Sc / 64, Bc * Hc);        // (32, 64)
    attn_kernel<<<ga, 256, ATTN_SMEM>>>((const float*)pQ, (const float*)pK,
                                        (const float*)pV, (float*)pC);

    gemm_mma_kernel<1><<<gg, 256>>>((const float*)pC, Wo, bo, out);
}